// round 1
// baseline (speedup 1.0000x reference)
#include <cuda_runtime.h>
#include <cstdint>

// Problem constants
// NT=32, HS=64, WS=64 (K of qkv GEMM), CL=96, OD=128, G=8
// b = nt*64 + hs in [0,2048)

__device__ float g_scratch[2048 * 64 * 96];  // scr[(b*64 + d)*96 + cl]

__device__ __forceinline__ unsigned long long ffma2(unsigned long long a,
                                                    unsigned long long b,
                                                    unsigned long long c) {
    unsigned long long d;
    asm("fma.rn.f32x2 %0, %1, %2, %3;" : "=l"(d) : "l"(a), "l"(b), "l"(c));
    return d;
}
__device__ __forceinline__ unsigned long long pack2(float lo, float hi) {
    unsigned long long r;
    asm("mov.b64 %0, {%1, %2};" : "=l"(r) : "f"(lo), "f"(hi));
    return r;
}
__device__ __forceinline__ float2 unpack2(unsigned long long v) {
    float2 f;
    asm("mov.b64 {%0, %1}, %2;" : "=f"(f.x), "=f"(f.y) : "l"(v));
    return f;
}

// Shared memory layout (float offsets). qk_s aliases w_s+xs (both dead after QKV).
#define OFF_QKV 0        // 128*96 = 12288
#define OFF_W   12288    // 64*130 = 8320   (w_s[i*130 + o], padded for banks+align)
#define OFF_XS  20608    // 64*97  = 6208   (xs[i*97 + l])
#define OFF_QK  12288    // 96*98  = 9408   (qk_s[i*98 + j], aliases W/XS region)
#define OFF_AQ  26816    // 128
#define OFF_BQ  26944    // 128
#define OFF_AS  27072    // 8
#define OFF_AO  27080    // 64
#define OFF_BO  27144    // 64
#define OFF_RS  27208    // 96
#define SMEM_FLOATS 27304
#define SMEM_BYTES (SMEM_FLOATS * 4)

extern "C" __global__ void __launch_bounds__(256, 2)
attn_fused_kernel(const float* __restrict__ x, const float* __restrict__ w_qkv,
                  const float* __restrict__ qg, const float* __restrict__ qb,
                  const float* __restrict__ qm, const float* __restrict__ qv,
                  const float* __restrict__ sg, const float* __restrict__ sb,
                  const float* __restrict__ smn, const float* __restrict__ svr,
                  const float* __restrict__ og, const float* __restrict__ ob,
                  const float* __restrict__ om, const float* __restrict__ ov) {
    extern __shared__ float smem[];
    const int tid  = threadIdx.x;
    const int lane = tid & 31;
    const int w    = tid >> 5;
    const int b    = blockIdx.x;
    const int nt   = b >> 6;
    const int hs   = b & 63;

    // ---- BN coefficient precompute ----
    if (tid < 128) {
        float a = qg[tid] * rsqrtf(qv[tid] + 1e-5f);
        smem[OFF_AQ + tid] = a;
        smem[OFF_BQ + tid] = qb[tid] - qm[tid] * a;
    }
    if (tid < 64) {
        float a = og[tid] * rsqrtf(ov[tid] + 1e-5f);
        smem[OFF_AO + tid] = a;
        smem[OFF_BO + tid] = ob[tid] - om[tid] * a;
    }
    if (tid < 8) {
        smem[OFF_AS + tid] = sg[tid] * rsqrtf(svr[tid] + 1e-5f);
        (void)sb; (void)smn;  // sim BN bias cancels inside softmax
    }

    // ---- load W transposed: w_s[i*130 + o] = w[o*64 + i] ----
    for (int idx = tid; idx < 128 * 64; idx += 256) {
        int o = idx >> 6, i = idx & 63;
        smem[OFF_W + i * 130 + o] = w_qkv[idx];
    }

    // ---- load x tile: xs[i*97 + l] = x[nt*393216 + l*4096 + hs*64 + i] ----
    {
        const float* xbase = x + (size_t)nt * 393216 + (size_t)hs * 64;
        for (int idx = tid; idx < 1536; idx += 256) {
            int i4 = idx & 15, l = idx >> 4;
            float4 v = *(const float4*)(xbase + (size_t)l * 4096 + i4 * 4);
            float* dst = &smem[OFF_XS + (i4 * 4) * 97 + l];
            dst[0]      = v.x;
            dst[97]     = v.y;
            dst[2 * 97] = v.z;
            dst[3 * 97] = v.w;
        }
    }
    __syncthreads();

    // ---- QKV GEMM + BN: qkv[o][l] = sum_i w[o][i]*x[i][l] ----
    // warp w owns o in [w*16, w*16+16) as 8 float2-pairs; lane owns l = lane+32t
    {
        unsigned long long acc[8][3];
#pragma unroll
        for (int p = 0; p < 8; p++)
#pragma unroll
            for (int t = 0; t < 3; t++) acc[p][t] = 0ull;

        const float* ws0 = &smem[OFF_W + w * 16];
        const float* xs0 = &smem[OFF_XS + lane];
#pragma unroll 4
        for (int i = 0; i < 64; i++) {
            unsigned long long xv[3];
#pragma unroll
            for (int t = 0; t < 3; t++) {
                float xf = xs0[i * 97 + 32 * t];
                xv[t] = pack2(xf, xf);
            }
#pragma unroll
            for (int p = 0; p < 8; p++) {
                unsigned long long w2 =
                    *(const unsigned long long*)(ws0 + i * 130 + 2 * p);
#pragma unroll
                for (int t = 0; t < 3; t++) acc[p][t] = ffma2(w2, xv[t], acc[p][t]);
            }
        }
#pragma unroll
        for (int p = 0; p < 8; p++) {
            int o0 = w * 16 + 2 * p;
            float a0 = smem[OFF_AQ + o0],     b0 = smem[OFF_BQ + o0];
            float a1 = smem[OFF_AQ + o0 + 1], b1 = smem[OFF_BQ + o0 + 1];
#pragma unroll
            for (int t = 0; t < 3; t++) {
                float2 r = unpack2(acc[p][t]);
                int l = lane + 32 * t;
                smem[OFF_QKV + o0 * 96 + l]       = r.x * a0 + b0;
                smem[OFF_QKV + (o0 + 1) * 96 + l] = r.y * a1 + b1;
            }
        }
    }
    __syncthreads();

    // ---- per-group attention ----
    for (int g = 0; g < 8; g++) {
        const float* qbase = &smem[OFF_QKV + (g * 16) * 96];
        const float* kbase = qbase + 4 * 96;
        const float* vbase = qbase + 8 * 96;
        const float ag = smem[OFF_AS + g];

        // QK: qk[i][j] = ag * sum_c q[c][i]*k[c][j]   (bias cancels in softmax)
        for (int idx = tid; idx < 1152; idx += 256) {
            int jp = idx % 48, i0 = idx / 48;  // i0 in [0,24); i = i0 + 24u
            unsigned long long acc[4] = {0ull, 0ull, 0ull, 0ull};
#pragma unroll
            for (int c = 0; c < 4; c++) {
                unsigned long long k2 =
                    *(const unsigned long long*)(kbase + c * 96 + 2 * jp);
#pragma unroll
                for (int u = 0; u < 4; u++) {
                    float q = qbase[c * 96 + i0 + 24 * u];
                    acc[u] = ffma2(pack2(q, q), k2, acc[u]);
                }
            }
#pragma unroll
            for (int u = 0; u < 4; u++) {
                float2 r = unpack2(acc[u]);
                float2* dst = (float2*)&smem[OFF_QK + (i0 + 24 * u) * 98 + 2 * jp];
                *dst = make_float2(r.x * ag, r.y * ag);
            }
        }
        __syncthreads();

        // softmax over j: warp w owns rows [w*12, w*12+12)
        for (int k = 0; k < 12; k++) {
            int r = w * 12 + k;
            float* row = &smem[OFF_QK + r * 98];
            float e0 = row[lane], e1 = row[lane + 32], e2 = row[lane + 64];
            float m = fmaxf(e0, fmaxf(e1, e2));
#pragma unroll
            for (int s = 16; s > 0; s >>= 1)
                m = fmaxf(m, __shfl_xor_sync(0xffffffffu, m, s));
            e0 = __expf(e0 - m);
            e1 = __expf(e1 - m);
            e2 = __expf(e2 - m);
            float ssum = e0 + e1 + e2;
#pragma unroll
            for (int s = 16; s > 0; s >>= 1)
                ssum += __shfl_xor_sync(0xffffffffu, ssum, s);
            row[lane]      = e0;
            row[lane + 32] = e1;
            row[lane + 64] = e2;
            if (lane == 0) smem[OFF_RS + r] = 1.0f / ssum;
        }
        __syncthreads();

        // SV: sv[c][i] = rsum[i] * sum_j e[i][j]*v[c][j]; + out BN; write scratch
        if (tid < 96) {
            int i = tid;
            unsigned long long acc[8];
#pragma unroll
            for (int c = 0; c < 8; c++) acc[c] = 0ull;
            const float* srow = &smem[OFF_QK + i * 98];
            for (int jp = 0; jp < 48; jp += 2) {
                unsigned long long s0 = *(const unsigned long long*)(srow + 2 * jp);
                unsigned long long s1 = *(const unsigned long long*)(srow + 2 * jp + 2);
#pragma unroll
                for (int c = 0; c < 8; c++) {
                    ulonglong2 vv = *(const ulonglong2*)(vbase + c * 96 + 2 * jp);
                    acc[c] = ffma2(s0, vv.x, acc[c]);
                    acc[c] = ffma2(s1, vv.y, acc[c]);
                }
            }
            float rs = smem[OFF_RS + i];
            float* scr = &g_scratch[(size_t)b * 64 * 96];
#pragma unroll
            for (int c = 0; c < 8; c++) {
                float2 r = unpack2(acc[c]);
                int d = g * 8 + c;
                float val = (r.x + r.y) * rs;
                scr[d * 96 + i] = val * smem[OFF_AO + d] + smem[OFF_BO + d];
            }
        }
        __syncthreads();
    }
}

// Permute scr[(nt*64+hs)*64*96 + d*96 + cl] -> out[((nt*96+cl)*64 + d)*64 + hs]
extern "C" __global__ void __launch_bounds__(256)
attn_transpose_kernel(float* __restrict__ out) {
    __shared__ float tile[64 * 97];
    const int nt = blockIdx.x >> 6;
    const int d  = blockIdx.x & 63;

    const float* src = g_scratch + (size_t)nt * 393216 + (size_t)d * 96;
    for (int idx = threadIdx.x; idx < 64 * 96; idx += 256) {
        int h = idx / 96, cl = idx % 96;
        tile[h * 97 + cl] = src[(size_t)h * 6144 + cl];
    }
    __syncthreads();

    float* dst = out + (size_t)nt * 393216 + (size_t)d * 64;
    for (int idx = threadIdx.x; idx < 64 * 96; idx += 256) {
        int cl = idx >> 6, h = idx & 63;
        dst[(size_t)cl * 4096 + h] = tile[h * 97 + cl];
    }
}

extern "C" void kernel_launch(void* const* d_in, const int* in_sizes, int n_in,
                              void* d_out, int out_size) {
    const float* x   = (const float*)d_in[0];
    const float* wq  = (const float*)d_in[1];
    const float* qg  = (const float*)d_in[2];
    const float* qb  = (const float*)d_in[3];
    const float* qm  = (const float*)d_in[4];
    const float* qv  = (const float*)d_in[5];
    const float* sg  = (const float*)d_in[6];
    const float* sb  = (const float*)d_in[7];
    const float* smn = (const float*)d_in[8];
    const float* svr = (const float*)d_in[9];
    const float* og  = (const float*)d_in[10];
    const float* ob  = (const float*)d_in[11];
    const float* om  = (const float*)d_in[12];
    const float* ov  = (const float*)d_in[13];
    float* out = (float*)d_out;

    cudaFuncSetAttribute(attn_fused_kernel,
                         cudaFuncAttributeMaxDynamicSharedMemorySize, SMEM_BYTES);

    attn_fused_kernel<<<2048, 256, SMEM_BYTES>>>(x, wq, qg, qb, qm, qv, sg, sb,
                                                 smn, svr, og, ob, om, ov);
    attn_transpose_kernel<<<2048, 256>>>(out);
}

// round 2
// speedup vs baseline: 2.4166x; 2.4166x over previous
#include <cuda_runtime.h>
#include <cstdint>

// NT=32, HS=64, WS=64 (K of qkv GEMM), CL=96, OD=128, G=8
// b = nt*64 + hs in [0,2048)

__device__ __align__(16) float g_scratch[2048 * 64 * 96];  // scr[b*6144 + d*96 + cl]

__device__ __forceinline__ unsigned long long ffma2(unsigned long long a,
                                                    unsigned long long b,
                                                    unsigned long long c) {
    unsigned long long d;
    asm("fma.rn.f32x2 %0, %1, %2, %3;" : "=l"(d) : "l"(a), "l"(b), "l"(c));
    return d;
}
__device__ __forceinline__ unsigned long long mul2(unsigned long long a,
                                                   unsigned long long b) {
    unsigned long long d;
    asm("mul.rn.f32x2 %0, %1, %2;" : "=l"(d) : "l"(a), "l"(b));
    return d;
}
__device__ __forceinline__ unsigned long long pack2(float lo, float hi) {
    unsigned long long r;
    asm("mov.b64 %0, {%1, %2};" : "=l"(r) : "f"(lo), "f"(hi));
    return r;
}
__device__ __forceinline__ float2 unpack2(unsigned long long v) {
    float2 f;
    asm("mov.b64 {%0, %1}, %2;" : "=f"(f.x), "=f"(f.y) : "l"(v));
    return f;
}
__device__ __forceinline__ float ex2f(float x) {
    float r;
    asm("ex2.approx.f32 %0, %1;" : "=f"(r) : "f"(x));
    return r;
}

// Shared memory layout (float offsets)
#define OFF_W   0        // 64*132 = 8448   w_s[i*132 + o]
#define OFF_XS  8448     // 64*97  = 6208   xs[i*97 + l]
#define OFF_QKV 14656    // 96*140 = 13440  qkvs[l*140 + o]  (transposed!)
#define OFF_AQ  28096    // 128
#define OFF_BQ  28224    // 128
#define OFF_AS  28352    // 8
#define OFF_AO  28360    // 64
#define OFF_BO  28424    // 64
#define SMEM_FLOATS 28488
#define SMEM_BYTES (SMEM_FLOATS * 4)

extern "C" __global__ void __launch_bounds__(256, 2)
attn_fused_kernel(const float* __restrict__ x, const float* __restrict__ w_qkv,
                  const float* __restrict__ qg, const float* __restrict__ qb,
                  const float* __restrict__ qm, const float* __restrict__ qv,
                  const float* __restrict__ sg, const float* __restrict__ sb,
                  const float* __restrict__ smn, const float* __restrict__ svr,
                  const float* __restrict__ og, const float* __restrict__ ob,
                  const float* __restrict__ om, const float* __restrict__ ov) {
    extern __shared__ float smem[];
    const int tid  = threadIdx.x;
    const int lane = tid & 31;
    const int w    = tid >> 5;
    const int b    = blockIdx.x;
    const int nt   = b >> 6;
    const int hs   = b & 63;

    // ---- BN coefficient precompute ----
    if (tid < 128) {
        float a = qg[tid] * rsqrtf(qv[tid] + 1e-5f);
        smem[OFF_AQ + tid] = a;
        smem[OFF_BQ + tid] = qb[tid] - qm[tid] * a;
    }
    if (tid < 64) {
        float a = og[tid] * rsqrtf(ov[tid] + 1e-5f);
        smem[OFF_AO + tid] = a;
        smem[OFF_BO + tid] = ob[tid] - om[tid] * a;
    }
    if (tid < 8) {
        smem[OFF_AS + tid] = sg[tid] * rsqrtf(svr[tid] + 1e-5f);
        (void)sb; (void)smn;  // sim BN bias cancels inside softmax
    }

    // ---- load W transposed: w_s[i*132 + o] = w[o*64 + i] ----
    for (int idx = tid; idx < 128 * 64; idx += 256) {
        int o = idx >> 6, i = idx & 63;
        smem[OFF_W + i * 132 + o] = w_qkv[idx];
    }

    // ---- load x tile: xs[i*97 + l] = x[nt*393216 + l*4096 + hs*64 + i] ----
    {
        const float* xbase = x + (size_t)nt * 393216 + (size_t)hs * 64;
        for (int idx = tid; idx < 1536; idx += 256) {
            int i4 = idx & 15, l = idx >> 4;
            float4 v = *(const float4*)(xbase + (size_t)l * 4096 + i4 * 4);
            float* dst = &smem[OFF_XS + (i4 * 4) * 97 + l];
            dst[0]      = v.x;
            dst[97]     = v.y;
            dst[2 * 97] = v.z;
            dst[3 * 97] = v.w;
        }
    }
    __syncthreads();

    // ---- QKV GEMM + BN, stored TRANSPOSED: qkvs[l*140 + o] ----
    // warp w owns o in [w*16, w*16+16) as 8 float2-pairs; lane owns l = lane+32t
    {
        unsigned long long acc[8][3];
#pragma unroll
        for (int p = 0; p < 8; p++)
#pragma unroll
            for (int t = 0; t < 3; t++) acc[p][t] = 0ull;

        const float* ws0 = &smem[OFF_W + w * 16];
        const float* xs0 = &smem[OFF_XS + lane];
#pragma unroll 4
        for (int i = 0; i < 64; i++) {
            unsigned long long xv[3];
#pragma unroll
            for (int t = 0; t < 3; t++) {
                float xf = xs0[i * 97 + 32 * t];
                xv[t] = pack2(xf, xf);
            }
#pragma unroll
            for (int p4 = 0; p4 < 4; p4++) {
                ulonglong2 w4 = *(const ulonglong2*)(ws0 + i * 132 + 4 * p4);
#pragma unroll
                for (int t = 0; t < 3; t++) {
                    acc[2 * p4][t]     = ffma2(w4.x, xv[t], acc[2 * p4][t]);
                    acc[2 * p4 + 1][t] = ffma2(w4.y, xv[t], acc[2 * p4 + 1][t]);
                }
            }
        }
#pragma unroll
        for (int p = 0; p < 8; p++) {
            int o0 = w * 16 + 2 * p;
            float a0 = smem[OFF_AQ + o0],     b0 = smem[OFF_BQ + o0];
            float a1 = smem[OFF_AQ + o0 + 1], b1 = smem[OFF_BQ + o0 + 1];
#pragma unroll
            for (int t = 0; t < 3; t++) {
                float2 r = unpack2(acc[p][t]);
                int l = lane + 32 * t;
                *(unsigned long long*)&smem[OFF_QKV + l * 140 + o0] =
                    pack2(r.x * a0 + b0, r.y * a1 + b1);
            }
        }
    }
    __syncthreads();

    // ---- attention: warp w handles group g = w, streaming over j ----
    // layout in qkvs row l: cols [g*16+0..3]=q, [4..7]=k, [8..15]=v
    {
        const int col0 = w * 16;
        const float sc = smem[OFF_AS + w] * 1.4426950408889634f;  // ag/ln2
        const unsigned long long sc2 = pack2(sc, sc);

        // preload q (scaled), lanes own i = lane + 32t
        unsigned long long qp[2][3];
#pragma unroll
        for (int cp = 0; cp < 2; cp++)
#pragma unroll
            for (int t = 0; t < 3; t++) {
                unsigned long long qraw = *(const unsigned long long*)
                    &smem[OFF_QKV + (lane + 32 * t) * 140 + col0 + 2 * cp];
                qp[cp][t] = mul2(qraw, sc2);
            }

        unsigned long long acc_sv[4][3];
#pragma unroll
        for (int cp = 0; cp < 4; cp++)
#pragma unroll
            for (int t = 0; t < 3; t++) acc_sv[cp][t] = 0ull;
        float s0 = 0.f, s1 = 0.f, s2 = 0.f;

#pragma unroll 4
        for (int j = 0; j < 96; j++) {
            const float* row = &smem[OFF_QKV + j * 140 + col0];
            ulonglong2 kk = *(const ulonglong2*)(row + 4);
            ulonglong2 va = *(const ulonglong2*)(row + 8);
            ulonglong2 vb = *(const ulonglong2*)(row + 12);
#pragma unroll
            for (int t = 0; t < 3; t++) {
                unsigned long long a2 =
                    ffma2(qp[1][t], kk.y, mul2(qp[0][t], kk.x));
                float2 f = unpack2(a2);
                float e = ex2f(f.x + f.y);           // exp(ag*qk), no max needed
                if (t == 0) s0 += e; else if (t == 1) s1 += e; else s2 += e;
                unsigned long long ee = pack2(e, e);
                acc_sv[0][t] = ffma2(ee, va.x, acc_sv[0][t]);
                acc_sv[1][t] = ffma2(ee, va.y, acc_sv[1][t]);
                acc_sv[2][t] = ffma2(ee, vb.x, acc_sv[2][t]);
                acc_sv[3][t] = ffma2(ee, vb.y, acc_sv[3][t]);
            }
        }

        // epilogue: normalize, out-BN, write scratch (coalesced over i=cl)
        float rs[3] = {1.f / s0, 1.f / s1, 1.f / s2};
        float* scr = &g_scratch[(size_t)b * 6144];
#pragma unroll
        for (int cp = 0; cp < 4; cp++) {
            int d0 = w * 8 + 2 * cp;
            float a0 = smem[OFF_AO + d0],     c0 = smem[OFF_BO + d0];
            float a1 = smem[OFF_AO + d0 + 1], c1 = smem[OFF_BO + d0 + 1];
#pragma unroll
            for (int t = 0; t < 3; t++) {
                float2 r = unpack2(acc_sv[cp][t]);
                int i = lane + 32 * t;
                scr[d0 * 96 + i]       = r.x * rs[t] * a0 + c0;
                scr[(d0 + 1) * 96 + i] = r.y * rs[t] * a1 + c1;
            }
        }
    }
}

// Permute scr[(nt*64+hs)*6144 + d*96 + cl] -> out[((nt*96+cl)*64 + d)*64 + hs]
extern "C" __global__ void __launch_bounds__(256)
attn_transpose_kernel(float* __restrict__ out) {
    __shared__ float tile[64 * 97];
    const int nt = blockIdx.x >> 6;
    const int d  = blockIdx.x & 63;

    const float* src = g_scratch + (size_t)nt * 393216 + (size_t)d * 96;
    for (int idx = threadIdx.x; idx < 64 * 24; idx += 256) {
        int h = idx / 24, c4 = idx % 24;
        float4 v = *(const float4*)(src + (size_t)h * 6144 + c4 * 4);
        float* dst = &tile[h * 97 + c4 * 4];
        dst[0] = v.x; dst[1] = v.y; dst[2] = v.z; dst[3] = v.w;
    }
    __syncthreads();

    float* dst = out + (size_t)nt * 393216 + (size_t)d * 64;
    for (int idx = threadIdx.x; idx < 64 * 96; idx += 256) {
        int cl = idx >> 6, h = idx & 63;
        dst[(size_t)cl * 4096 + h] = tile[h * 97 + cl];
    }
}

extern "C" void kernel_launch(void* const* d_in, const int* in_sizes, int n_in,
                              void* d_out, int out_size) {
    const float* x   = (const float*)d_in[0];
    const float* wq  = (const float*)d_in[1];
    const float* qg  = (const float*)d_in[2];
    const float* qb  = (const float*)d_in[3];
    const float* qm  = (const float*)d_in[4];
    const float* qv  = (const float*)d_in[5];
    const float* sg  = (const float*)d_in[6];
    const float* sb  = (const float*)d_in[7];
    const float* smn = (const float*)d_in[8];
    const float* svr = (const float*)d_in[9];
    const float* og  = (const float*)d_in[10];
    const float* ob  = (const float*)d_in[11];
    const float* om  = (const float*)d_in[12];
    const float* ov  = (const float*)d_in[13];
    float* out = (float*)d_out;

    cudaFuncSetAttribute(attn_fused_kernel,
                         cudaFuncAttributeMaxDynamicSharedMemorySize, SMEM_BYTES);

    attn_fused_kernel<<<2048, 256, SMEM_BYTES>>>(x, wq, qg, qb, qm, qv, sg, sb,
                                                 smn, svr, og, ob, om, ov);
    attn_transpose_kernel<<<2048, 256>>>(out);
}

// round 3
// speedup vs baseline: 2.4195x; 1.0012x over previous
#include <cuda_runtime.h>
#include <cstdint>

// NT=32, HS=64, WS=64 (K of qkv GEMM), CL=96, OD=128, G=8
// b = nt*64 + hs in [0,2048)

__device__ __align__(16) float g_scratch[2048 * 64 * 96];  // scr[b*6144 + d*96 + cl]

__device__ __forceinline__ unsigned long long ffma2(unsigned long long a,
                                                    unsigned long long b,
                                                    unsigned long long c) {
    unsigned long long d;
    asm("fma.rn.f32x2 %0, %1, %2, %3;" : "=l"(d) : "l"(a), "l"(b), "l"(c));
    return d;
}
__device__ __forceinline__ unsigned long long mul2(unsigned long long a,
                                                   unsigned long long b) {
    unsigned long long d;
    asm("mul.rn.f32x2 %0, %1, %2;" : "=l"(d) : "l"(a), "l"(b));
    return d;
}
__device__ __forceinline__ unsigned long long pack2(float lo, float hi) {
    unsigned long long r;
    asm("mov.b64 %0, {%1, %2};" : "=l"(r) : "f"(lo), "f"(hi));
    return r;
}
__device__ __forceinline__ float2 unpack2(unsigned long long v) {
    float2 f;
    asm("mov.b64 {%0, %1}, %2;" : "=f"(f.x), "=f"(f.y) : "l"(v));
    return f;
}
__device__ __forceinline__ float ex2f(float x) {
    float r;
    asm("ex2.approx.f32 %0, %1;" : "=f"(r) : "f"(x));
    return r;
}

// Shared memory layout (float offsets)
#define OFF_W   0        // 64*132 = 8448   w_s[i*132 + o]
#define OFF_XS  8448     // 64*97  = 6208   xs[i*97 + l]
#define OFF_QKV 14656    // 96*140 = 13440  qkvs[l*140 + o]  (only k,v cols used)
#define OFF_AQ  28096    // 128
#define OFF_BQ  28224    // 128
#define OFF_AS  28352    // 8
#define OFF_AO  28360    // 64
#define OFF_BO  28424    // 64
#define SMEM_FLOATS 28488
#define SMEM_BYTES (SMEM_FLOATS * 4)

extern "C" __global__ void __launch_bounds__(256, 2)
attn_fused_kernel(const float* __restrict__ x, const float* __restrict__ w_qkv,
                  const float* __restrict__ qg, const float* __restrict__ qb,
                  const float* __restrict__ qm, const float* __restrict__ qv,
                  const float* __restrict__ sg, const float* __restrict__ sb,
                  const float* __restrict__ smn, const float* __restrict__ svr,
                  const float* __restrict__ og, const float* __restrict__ ob,
                  const float* __restrict__ om, const float* __restrict__ ov) {
    extern __shared__ float smem[];
    const int tid  = threadIdx.x;
    const int lane = tid & 31;
    const int w    = tid >> 5;
    const int b    = blockIdx.x;
    const int nt   = b >> 6;
    const int hs   = b & 63;

    // ---- issue x-tile LDGs first (hide DRAM latency behind W/BN work) ----
    // xr[u] <- x[nt*393216 + l*4096 + hs*64 + i4*4], idx = tid + 256u
    float4 xr[6];
    {
        const float* xbase = x + (size_t)nt * 393216 + (size_t)hs * 64;
#pragma unroll
        for (int u = 0; u < 6; u++) {
            int idx = tid + 256 * u;
            int i4 = idx & 15, l = idx >> 4;
            xr[u] = *(const float4*)(xbase + (size_t)l * 4096 + i4 * 4);
        }
    }

    // ---- BN coefficient precompute ----
    if (tid < 128) {
        float a = qg[tid] * rsqrtf(qv[tid] + 1e-5f);
        smem[OFF_AQ + tid] = a;
        smem[OFF_BQ + tid] = qb[tid] - qm[tid] * a;
    }
    if (tid < 64) {
        float a = og[tid] * rsqrtf(ov[tid] + 1e-5f);
        smem[OFF_AO + tid] = a;
        smem[OFF_BO + tid] = ob[tid] - om[tid] * a;
    }
    if (tid < 8) {
        smem[OFF_AS + tid] = sg[tid] * rsqrtf(svr[tid] + 1e-5f);
        (void)sb; (void)smn;  // sim BN bias cancels inside softmax
    }

    // ---- load W transposed: w_s[i*132 + o] = w[o*64 + i] (LDG.128) ----
#pragma unroll
    for (int u = 0; u < 8; u++) {
        int idx4 = tid + 256 * u;            // float4 index
        int o = idx4 >> 4, i0 = (idx4 & 15) * 4;
        float4 v = *(const float4*)(w_qkv + idx4 * 4);
        smem[OFF_W + (i0 + 0) * 132 + o] = v.x;
        smem[OFF_W + (i0 + 1) * 132 + o] = v.y;
        smem[OFF_W + (i0 + 2) * 132 + o] = v.z;
        smem[OFF_W + (i0 + 3) * 132 + o] = v.w;
    }

    // ---- store x tile: xs[i*97 + l] ----
#pragma unroll
    for (int u = 0; u < 6; u++) {
        int idx = tid + 256 * u;
        int i4 = idx & 15, l = idx >> 4;
        float* dst = &smem[OFF_XS + (i4 * 4) * 97 + l];
        dst[0]      = xr[u].x;
        dst[97]     = xr[u].y;
        dst[2 * 97] = xr[u].z;
        dst[3 * 97] = xr[u].w;
    }
    __syncthreads();

    const float sc = smem[OFF_AS + w] * 1.4426950408889634f;  // ag/ln2

    // ---- QKV GEMM + BN. Warp w owns o in [w*16, w*16+16) == group w's q,k,v.
    // q (p=0,1) stays in registers; k,v (p=2..7) go to smem transposed.
    unsigned long long qp[2][3];
    {
        unsigned long long acc[8][3];
#pragma unroll
        for (int p = 0; p < 8; p++)
#pragma unroll
            for (int t = 0; t < 3; t++) acc[p][t] = 0ull;

        const float* ws0 = &smem[OFF_W + w * 16];
        const float* xs0 = &smem[OFF_XS + lane];
#pragma unroll 4
        for (int i = 0; i < 64; i++) {
            unsigned long long xv[3];
#pragma unroll
            for (int t = 0; t < 3; t++) {
                float xf = xs0[i * 97 + 32 * t];
                xv[t] = pack2(xf, xf);
            }
#pragma unroll
            for (int p4 = 0; p4 < 4; p4++) {
                ulonglong2 w4 = *(const ulonglong2*)(ws0 + i * 132 + 4 * p4);
#pragma unroll
                for (int t = 0; t < 3; t++) {
                    acc[2 * p4][t]     = ffma2(w4.x, xv[t], acc[2 * p4][t]);
                    acc[2 * p4 + 1][t] = ffma2(w4.y, xv[t], acc[2 * p4 + 1][t]);
                }
            }
        }
        // q: BN fused with softmax scale, kept in registers (lane owns i = lane+32t)
#pragma unroll
        for (int p = 0; p < 2; p++) {
            int o0 = w * 16 + 2 * p;
            float a0 = smem[OFF_AQ + o0] * sc,     b0 = smem[OFF_BQ + o0] * sc;
            float a1 = smem[OFF_AQ + o0 + 1] * sc, b1 = smem[OFF_BQ + o0 + 1] * sc;
#pragma unroll
            for (int t = 0; t < 3; t++) {
                float2 r = unpack2(acc[p][t]);
                qp[p][t] = pack2(r.x * a0 + b0, r.y * a1 + b1);
            }
        }
        // k,v: BN, stored transposed qkvs[l*140 + o]
#pragma unroll
        for (int p = 2; p < 8; p++) {
            int o0 = w * 16 + 2 * p;
            float a0 = smem[OFF_AQ + o0],     b0 = smem[OFF_BQ + o0];
            float a1 = smem[OFF_AQ + o0 + 1], b1 = smem[OFF_BQ + o0 + 1];
#pragma unroll
            for (int t = 0; t < 3; t++) {
                float2 r = unpack2(acc[p][t]);
                int l = lane + 32 * t;
                *(unsigned long long*)&smem[OFF_QKV + l * 140 + o0] =
                    pack2(r.x * a0 + b0, r.y * a1 + b1);
            }
        }
    }
    __syncwarp();   // warp-local: attention reads only this warp's k,v writes

    // ---- attention: warp w == group w, streaming over j (flash-style) ----
    {
        const int col0 = w * 16;

        unsigned long long acc_sv[4][3];
#pragma unroll
        for (int cp = 0; cp < 4; cp++)
#pragma unroll
            for (int t = 0; t < 3; t++) acc_sv[cp][t] = 0ull;
        float s0 = 0.f, s1 = 0.f, s2 = 0.f;

#pragma unroll 4
        for (int j = 0; j < 96; j++) {
            const float* row = &smem[OFF_QKV + j * 140 + col0];
            ulonglong2 kk = *(const ulonglong2*)(row + 4);
            ulonglong2 va = *(const ulonglong2*)(row + 8);
            ulonglong2 vb = *(const ulonglong2*)(row + 12);
#pragma unroll
            for (int t = 0; t < 3; t++) {
                unsigned long long a2 =
                    ffma2(qp[1][t], kk.y, mul2(qp[0][t], kk.x));
                float2 f = unpack2(a2);
                float e = ex2f(f.x + f.y);           // exp(ag*qk), no max needed
                if (t == 0) s0 += e; else if (t == 1) s1 += e; else s2 += e;
                unsigned long long ee = pack2(e, e);
                acc_sv[0][t] = ffma2(ee, va.x, acc_sv[0][t]);
                acc_sv[1][t] = ffma2(ee, va.y, acc_sv[1][t]);
                acc_sv[2][t] = ffma2(ee, vb.x, acc_sv[2][t]);
                acc_sv[3][t] = ffma2(ee, vb.y, acc_sv[3][t]);
            }
        }

        // epilogue: normalize, out-BN, write scratch (coalesced over i=cl)
        float rs[3] = {1.f / s0, 1.f / s1, 1.f / s2};
        float* scr = &g_scratch[(size_t)b * 6144];
#pragma unroll
        for (int cp = 0; cp < 4; cp++) {
            int d0 = w * 8 + 2 * cp;
            float a0 = smem[OFF_AO + d0],     c0 = smem[OFF_BO + d0];
            float a1 = smem[OFF_AO + d0 + 1], c1 = smem[OFF_BO + d0 + 1];
#pragma unroll
            for (int t = 0; t < 3; t++) {
                float2 r = unpack2(acc_sv[cp][t]);
                int i = lane + 32 * t;
                scr[d0 * 96 + i]       = r.x * rs[t] * a0 + c0;
                scr[(d0 + 1) * 96 + i] = r.y * rs[t] * a1 + c1;
            }
        }
    }
}

// Permute scr[(nt*64+hs)*6144 + d*96 + cl] -> out[((nt*96+cl)*64 + d)*64 + hs]
extern "C" __global__ void __launch_bounds__(256)
attn_transpose_kernel(float* __restrict__ out) {
    __shared__ float tile[64 * 97];
    const int nt = blockIdx.x >> 6;
    const int d  = blockIdx.x & 63;

    const float* src = g_scratch + (size_t)nt * 393216 + (size_t)d * 96;
#pragma unroll
    for (int u = 0; u < 6; u++) {
        int idx = threadIdx.x + 256 * u;
        int h = idx / 24, c4 = idx % 24;
        float4 v = *(const float4*)(src + (size_t)h * 6144 + c4 * 4);
        float* dst = &tile[h * 97 + c4 * 4];
        dst[0] = v.x; dst[1] = v.y; dst[2] = v.z; dst[3] = v.w;
    }
    __syncthreads();

    float* dst = out + (size_t)nt * 393216 + (size_t)d * 64;
#pragma unroll
    for (int u = 0; u < 24; u++) {
        int idx = threadIdx.x + 256 * u;
        int cl = idx >> 6, h = idx & 63;
        dst[(size_t)cl * 4096 + h] = tile[h * 97 + cl];
    }
}

extern "C" void kernel_launch(void* const* d_in, const int* in_sizes, int n_in,
                              void* d_out, int out_size) {
    const float* x   = (const float*)d_in[0];
    const float* wq  = (const float*)d_in[1];
    const float* qg  = (const float*)d_in[2];
    const float* qb  = (const float*)d_in[3];
    const float* qm  = (const float*)d_in[4];
    const float* qv  = (const float*)d_in[5];
    const float* sg  = (const float*)d_in[6];
    const float* sb  = (const float*)d_in[7];
    const float* smn = (const float*)d_in[8];
    const float* svr = (const float*)d_in[9];
    const float* og  = (const float*)d_in[10];
    const float* ob  = (const float*)d_in[11];
    const float* om  = (const float*)d_in[12];
    const float* ov  = (const float*)d_in[13];
    float* out = (float*)d_out;

    cudaFuncSetAttribute(attn_fused_kernel,
                         cudaFuncAttributeMaxDynamicSharedMemorySize, SMEM_BYTES);

    attn_fused_kernel<<<2048, 256, SMEM_BYTES>>>(x, wq, qg, qb, qm, qv, sg, sb,
                                                 smn, svr, og, ob, om, ov);
    attn_transpose_kernel<<<2048, 256>>>(out);
}